// round 6
// baseline (speedup 1.0000x reference)
#include <cuda_runtime.h>
#include <cstdint>

// ----------------------------------------------------------------------------
// LightOnOCRPatchMerger via int8 fixed-point split mma.sync (tcgen05 is
// unavailable: harness compiles PTX for plain sm_103, no 'a' features).
//   out[11955,1024] = merged[11955,4096] @ W[1024,4096]^T
// a = (a1*128 + a0)/2^11, b = (b1*128 + b0)/2^17  (int8 planes, prep kernels)
// out = (16384*HH + 128*CR)/2^28, HH = sum a1b1, CR = sum (a1b0 + a0b1),
// a0b0 dropped (rel ~2.5e-4). One s32 accumulator: acc = HH; acc <<= 7; += CR.
// 3 K-passes x 32 chunks of K=128 int8. Block 128x256, 512 thr, 16 warps of
// warp-tile 32x64, 4-stage cp.async pipeline, persistent grid 148.
// K is sub-major (kg = sub*1024 + d) so A rows are contiguous token-row reads.
// ----------------------------------------------------------------------------

#define M_TOTAL 11955
#define CHUNKS  96          // 3 passes * 32 chunks(K=128)
#define NSTAGE  4
#define STAGE_B 49152       // A 16KB + B 32KB
#define SMEM_TOTAL (2048 + NSTAGE * STAGE_B)   // 198656

// int8 planes (device globals; no allocation)
__device__ int8_t gA1[(size_t)47820 * 1024];
__device__ int8_t gA0[(size_t)47820 * 1024];
__device__ int8_t gB1[(size_t)1024 * 4096];
__device__ int8_t gB0[(size_t)1024 * 4096];

__device__ __forceinline__ void quant2(float x, float S, int& hi, int& lo) {
    int q = __float2int_rn(x * S);
    q = q < -16320 ? -16320 : (q > 16319 ? 16319 : q);
    hi = (q + 64) >> 7;          // [-127,127]
    lo = q - (hi << 7);          // [-64,63]
}
__device__ __forceinline__ unsigned pack4(int a, int b, int c, int d) {
    return (unsigned)(a & 255) | ((unsigned)(b & 255) << 8) |
           ((unsigned)(c & 255) << 16) | ((unsigned)(d & 255) << 24);
}
// k-interleave within each 32B group: granule tig holds k{4t..4t+3, 16+4t..}
// dest dword for a 4-aligned quad at k: (k>>5)*8 + ((k>>2)&3)*2 + ((k>>4)&1)
__device__ __forceinline__ int destdw(int k) {
    return (k >> 5) * 8 + ((k >> 2) & 3) * 2 + ((k >> 4) & 1);
}

__global__ void prep_feat(const float* __restrict__ F) {
    int idx = blockIdx.x * 256 + threadIdx.x;    // 47820*256
    int tok = idx >> 8, d = (idx & 255) * 4;
    float4 v = *(const float4*)(F + (size_t)tok * 1024 + d);
    int h0, l0, h1, l1, h2, l2, h3, l3;
    quant2(v.x, 2048.f, h0, l0);  quant2(v.y, 2048.f, h1, l1);
    quant2(v.z, 2048.f, h2, l2);  quant2(v.w, 2048.f, h3, l3);
    size_t o = (size_t)tok * 256 + destdw(d);
    ((unsigned*)gA1)[o] = pack4(h0, h1, h2, h3);
    ((unsigned*)gA0)[o] = pack4(l0, l1, l2, l3);
}

__global__ void prep_w(const float* __restrict__ W) {
    int idx = blockIdx.x * 256 + threadIdx.x;    // 1024*1024
    int o = idx >> 10, kg = (idx & 1023) * 4;
    int sub = kg >> 10, dd = kg & 1023;
    const float* src = W + (size_t)o * 4096 + sub;
    int h[4], l[4];
    #pragma unroll
    for (int r = 0; r < 4; r++)
        quant2(src[(dd + r) * 4], 131072.f, h[r], l[r]);
    size_t q = (size_t)o * 1024 + destdw(kg);
    ((unsigned*)gB1)[q] = pack4(h[0], h[1], h[2], h[3]);
    ((unsigned*)gB0)[q] = pack4(l[0], l[1], l[2], l[3]);
}

__device__ __forceinline__ void imma(int* d, const unsigned* a, const unsigned* b) {
    asm volatile(
        "mma.sync.aligned.m16n8k32.row.col.s32.s8.s8.s32 "
        "{%0,%1,%2,%3}, {%4,%5,%6,%7}, {%8,%9}, {%0,%1,%2,%3};"
        : "+r"(d[0]), "+r"(d[1]), "+r"(d[2]), "+r"(d[3])
        : "r"(a[0]), "r"(a[1]), "r"(a[2]), "r"(a[3]), "r"(b[0]), "r"(b[1]));
}

__global__ __launch_bounds__(512, 1)
void merger_imma(float* __restrict__ out) {
    extern __shared__ char smem[];
    int* rowTok = (int*)smem;                      // [4][128]
    const unsigned sbase = (unsigned)__cvta_generic_to_shared(smem);
    const unsigned sstage = sbase + 2048;

    const int tid = threadIdx.x, lane = tid & 31, w = tid >> 5;
    const int wm = w & 3, wn = w >> 2;             // 4 M-warps x 4 N-warps
    const int g = lane >> 2, tig = lane & 3;

    for (int tile = blockIdx.x; tile < 376; tile += gridDim.x) {
        const int nt = tile & 3, mt = tile >> 2;
        __syncthreads();                            // quiesce previous tile

        if (tid < 128) {
            int r = mt * 128 + tid;
            if (r >= M_TOTAL) r = M_TOTAL - 1;
            const int boff[6] = {0, 2420, 4620, 6060, 9085, 10525};
            const int toff[6] = {0, 9680, 18480, 24240, 36340, 42100};
            const int gw[6]   = {88, 110, 90, 110, 64, 110};
            const int nbw[6]  = {44, 55, 45, 55, 32, 55};
            int img = 0;
            #pragma unroll
            for (int i = 1; i < 6; i++) if (r >= boff[i]) img = i;
            int local = r - boff[img];
            int bh = local / nbw[img];
            int bw = local - bh * nbw[img];
            int wd = gw[img];
            int base = toff[img] + 2 * bh * wd + 2 * bw;
            rowTok[0 * 128 + tid] = base;
            rowTok[1 * 128 + tid] = base + 1;
            rowTok[2 * 128 + tid] = base + wd;
            rowTok[3 * 128 + tid] = base + wd + 1;
        }
        __syncthreads();

        int acc[2][8][4];
        #pragma unroll
        for (int f = 0; f < 2; f++)
            #pragma unroll
            for (int c = 0; c < 8; c++)
                #pragma unroll
                for (int i = 0; i < 4; i++) acc[f][c][i] = 0;

        // producer: chunk lit -> stage lit&3.  pass planes:
        //   lit<32: a1*b1   32<=lit<64: a1*b0   lit>=64: a0*b1
        auto issue = [&](int lit) {
            int c = lit & 31, sub = c >> 3, d0 = (c & 7) << 7;
            const int8_t* Apl = (lit < 64) ? gA1 : gA0;
            const int8_t* Bpl = (lit < 32 || lit >= 64) ? gB1 : gB0;
            unsigned stA = sstage + (lit & 3) * STAGE_B;
            unsigned stB = stA + 16384;
            #pragma unroll
            for (int i = 0; i < 2; i++) {          // A: 1024 granules
                int gi = tid * 2 + i;
                int r = gi >> 3, G = gi & 7;
                const int8_t* src = Apl + (size_t)rowTok[sub * 128 + r] * 1024 + d0 + G * 16;
                unsigned dst = stA + r * 128 + ((G ^ (r & 7)) << 4);
                asm volatile("cp.async.cg.shared.global [%0],[%1],16;"
                             :: "r"(dst), "l"(src) : "memory");
            }
            #pragma unroll
            for (int i = 0; i < 4; i++) {          // B: 2048 granules
                int gi = tid + (i << 9);
                int n = gi >> 3, G = gi & 7;
                const int8_t* src = Bpl + (size_t)(nt * 256 + n) * 4096 + (c << 7) + G * 16;
                unsigned dst = stB + n * 128 + ((G ^ (n & 7)) << 4);
                asm volatile("cp.async.cg.shared.global [%0],[%1],16;"
                             :: "r"(dst), "l"(src) : "memory");
            }
            asm volatile("cp.async.commit_group;" ::: "memory");
        };

        issue(0); issue(1); issue(2);

        #pragma unroll 1
        for (int it = 0; it < CHUNKS; it++) {
            asm volatile("cp.async.wait_group 2;" ::: "memory");
            __syncthreads();
            int lit = it + 3;
            if (lit < CHUNKS) issue(lit);
            else asm volatile("cp.async.commit_group;" ::: "memory");

            unsigned sA = sstage + (it & 3) * STAGE_B;
            unsigned sB = sA + 16384;
            #pragma unroll
            for (int ks = 0; ks < 4; ks++) {
                unsigned G = ks * 2 + (tig >> 1);
                unsigned o8 = (tig & 1) << 3;
                unsigned a[2][4];
                #pragma unroll
                for (int f = 0; f < 2; f++) {
                    int r0 = wm * 32 + f * 16 + g;      // (r0+8)&7 == r0&7
                    unsigned ad = sA + r0 * 128 + ((G ^ (r0 & 7)) << 4) + o8;
                    asm volatile("ld.shared.v2.u32 {%0,%1},[%2];"
                                 : "=r"(a[f][0]), "=r"(a[f][2]) : "r"(ad));
                    asm volatile("ld.shared.v2.u32 {%0,%1},[%2];"
                                 : "=r"(a[f][1]), "=r"(a[f][3]) : "r"(ad + 1024));
                }
                #pragma unroll
                for (int c = 0; c < 8; c++) {
                    int rb = wn * 64 + c * 8 + g;
                    unsigned bd = sB + rb * 128 + ((G ^ (rb & 7)) << 4) + o8;
                    unsigned b[2];
                    asm volatile("ld.shared.v2.u32 {%0,%1},[%2];"
                                 : "=r"(b[0]), "=r"(b[1]) : "r"(bd));
                    imma(acc[0][c], a[0], b);
                    imma(acc[1][c], a[1], b);
                }
            }
            if (it == 31) {                         // acc = 128*HH, then += CR
                #pragma unroll
                for (int f = 0; f < 2; f++)
                    #pragma unroll
                    for (int c = 0; c < 8; c++)
                        #pragma unroll
                        for (int i = 0; i < 4; i++) acc[f][c][i] <<= 7;
            }
        }

        // epilogue: out = acc * 2^-21  (= 128/(2^11 * 2^17))
        const float sc = 4.76837158203125e-7f;
        #pragma unroll
        for (int f = 0; f < 2; f++) {
            int m = mt * 128 + wm * 32 + f * 16 + g;
            #pragma unroll
            for (int c = 0; c < 8; c++) {
                int n = nt * 256 + wn * 64 + c * 8 + (tig << 1);
                if (m < M_TOTAL) {
                    float2 v = make_float2(acc[f][c][0] * sc, acc[f][c][1] * sc);
                    *(float2*)(out + (size_t)m * 1024 + n) = v;
                }
                if (m + 8 < M_TOTAL) {
                    float2 v = make_float2(acc[f][c][2] * sc, acc[f][c][3] * sc);
                    *(float2*)(out + (size_t)(m + 8) * 1024 + n) = v;
                }
            }
        }
    }
}

extern "C" void kernel_launch(void* const* d_in, const int* in_sizes, int n_in,
                              void* d_out, int out_size) {
    const float* feat = (const float*)d_in[0];   // [47820, 1024] fp32
    const float* W    = (const float*)d_in[1];   // [1024, 4096] fp32
    float* out = (float*)d_out;                  // [11955, 1024] fp32

    prep_feat<<<47820, 256>>>(feat);
    prep_w<<<4096, 256>>>(W);

    cudaFuncSetAttribute(merger_imma,
                         cudaFuncAttributeMaxDynamicSharedMemorySize, SMEM_TOTAL);
    merger_imma<<<148, 512, SMEM_TOTAL>>>(out);
}

// round 7
// speedup vs baseline: 3.5744x; 3.5744x over previous
#include <cuda_runtime.h>
#include <cstdint>

// ----------------------------------------------------------------------------
// LightOnOCRPatchMerger, round 7: tf32 mma.sync GEMM with all marshaling
// moved to prep kernels.
//   out[11955,1024] = merged[11955,4096] @ W[1024,4096]^T   (K sub-major)
// Prep writes both operands chunk-major (BK=32), k-interleaved and
// XOR-swizzled so that (a) each stage is ONE contiguous cp.async.bulk per
// operand and (b) fragment loads are conflict-free LDS.64.
// GEMM: 512 threads, tile 256x128, 16 warps of 32x64, 3-stage mbarrier ring.
// ----------------------------------------------------------------------------

#define M_TOTAL 11955
#define M_PAD   12032          // 47 tiles of 256
#define NCHUNK  128            // K=4096 / 32
#define STAGE_A 32768          // 256 rows * 128B
#define STAGE_B 16384          // 128 rows * 128B
#define STAGE_T 49152
#define NSTAGE  3
#define SMEM_DYN (NSTAGE * STAGE_T)   // 147456

// [chunk][row][granule] 16B granules. Within a row's 32 k-values (k = kl):
// tig = kl&3, j = kl>>2, h = j>>2, slot = j&3; storage granule P satisfies
// (2*tig + h) = P ^ (row & 7); float slot within granule = slot.
__device__ float4 gA[(size_t)NCHUNK * M_PAD * 8];   // 197 MB
__device__ float4 gB[(size_t)NCHUNK * 1024 * 8];    // 16 MB

__device__ __forceinline__ float rna_tf32(float x) {
    unsigned u; asm("cvt.rna.tf32.f32 %0, %1;" : "=r"(u) : "f"(x));
    return __uint_as_float(u);
}

// token index for merged row m, sub-position sub (geometry from IMAGE_SIZES)
__device__ __forceinline__ int tok_of(int m, int sub) {
    const int boff[6] = {0, 2420, 4620, 6060, 9085, 10525};
    const int toff[6] = {0, 9680, 18480, 24240, 36340, 42100};
    const int gw[6]   = {88, 110, 90, 110, 64, 110};
    const int nbw[6]  = {44, 55, 45, 55, 32, 55};
    int img = 0;
    #pragma unroll
    for (int i = 1; i < 6; i++) if (m >= boff[i]) img = i;
    int local = m - boff[img];
    int bh = local / nbw[img], bw = local - bh * nbw[img];
    int w = gw[img];
    return toff[img] + 2 * bh * w + 2 * bw + (sub >> 1) * w + (sub & 1);
}

__global__ void prep_A(const float* __restrict__ F) {
    int idx = blockIdx.x * 256 + threadIdx.x;   // [0, 96256): m*8 + gidx
    int c = blockIdx.y;
    int m = idx >> 3, gidx = idx & 7;
    int mc = m < M_TOTAL ? m : M_TOTAL - 1;
    int pos = gidx ^ (m & 7);
    int tig = pos >> 1, h = pos & 1;
    int sub = c >> 5;
    int dbase = (c & 31) * 32 + tig + 16 * h;
    const float* src = F + (size_t)tok_of(mc, sub) * 1024 + dbase;
    float4 v;
    v.x = rna_tf32(src[0]);  v.y = rna_tf32(src[4]);
    v.z = rna_tf32(src[8]);  v.w = rna_tf32(src[12]);
    gA[((size_t)c * M_PAD + m) * 8 + gidx] = v;
}

__global__ void prep_B(const float* __restrict__ W) {
    int idx = blockIdx.x * 256 + threadIdx.x;   // [0, 8192): n*8 + gidx
    int c = blockIdx.y;
    int n = idx >> 3, gidx = idx & 7;
    int pos = gidx ^ (n & 7);
    int tig = pos >> 1, h = pos & 1;
    int sub = c >> 5;
    int kbase = (c & 31) * 32 + tig + 16 * h;   // d index; W col = d*4 + sub
    const float* src = W + (size_t)n * 4096 + sub;
    float4 v;
    v.x = rna_tf32(src[(kbase + 0) * 4]);
    v.y = rna_tf32(src[(kbase + 4) * 4]);
    v.z = rna_tf32(src[(kbase + 8) * 4]);
    v.w = rna_tf32(src[(kbase + 12) * 4]);
    gB[((size_t)c * 1024 + n) * 8 + gidx] = v;
}

__device__ __forceinline__ void mma_tf32(float* d, const unsigned* a, const unsigned* b) {
    asm volatile(
        "mma.sync.aligned.m16n8k8.row.col.f32.tf32.tf32.f32 "
        "{%0,%1,%2,%3}, {%4,%5,%6,%7}, {%8,%9}, {%0,%1,%2,%3};"
        : "+f"(d[0]), "+f"(d[1]), "+f"(d[2]), "+f"(d[3])
        : "r"(a[0]), "r"(a[1]), "r"(a[2]), "r"(a[3]), "r"(b[0]), "r"(b[1]));
}

#define WAITP(a, ph) \
    asm volatile("{\n\t.reg .pred P;\n\tWL%=:\n\t" \
        "mbarrier.try_wait.parity.acquire.cta.shared::cta.b64 P, [%0], %1, 0x989680;\n\t" \
        "@P bra.uni WD%=;\n\tbra.uni WL%=;\n\tWD%=:\n\t}" :: "r"(a), "r"(ph) : "memory")

__global__ void __launch_bounds__(512, 1)
merger_gemm(float* __restrict__ out) {
    extern __shared__ float4 stg[];
    __shared__ uint64_t mbar[NSTAGE];
    unsigned sbase, mb;
    asm("{ .reg .u64 t; cvta.to.shared.u64 t, %1; cvt.u32.u64 %0, t; }"
        : "=r"(sbase) : "l"((void*)stg));
    asm("{ .reg .u64 t; cvta.to.shared.u64 t, %1; cvt.u32.u64 %0, t; }"
        : "=r"(mb) : "l"((void*)mbar));

    const int tid = threadIdx.x, lane = tid & 31, w = tid >> 5;
    const int wm = w >> 1, wn = w & 1;        // 8 M-warps x 2 N-warps
    const int g = lane >> 2, tig = lane & 3;
    const int nt = blockIdx.x, mt = blockIdx.y;

    if (tid == 0) {
        #pragma unroll
        for (int s = 0; s < NSTAGE; s++)
            asm volatile("mbarrier.init.shared.b64 [%0], 1;"
                         :: "r"(mb + s * 8) : "memory");
    }
    asm volatile("fence.proxy.async;" ::: "memory");
    __syncthreads();

    const char* srcA0 = (const char*)(gA + ((size_t)0 * M_PAD + mt * 256) * 8);
    const char* srcB0 = (const char*)(gB + ((size_t)0 * 1024 + nt * 128) * 8);

    auto issue = [&](int chunk, int slot) {
        unsigned bar = mb + slot * 8;
        asm volatile("mbarrier.arrive.expect_tx.shared.b64 _, [%0], %1;"
                     :: "r"(bar), "r"((unsigned)STAGE_T) : "memory");
        const char* sa = srcA0 + (size_t)chunk * (M_PAD * 128);
        const char* sb = srcB0 + (size_t)chunk * (1024 * 128);
        unsigned da = sbase + slot * STAGE_T;
        asm volatile("cp.async.bulk.shared::cluster.global.mbarrier::complete_tx::bytes "
                     "[%0], [%1], %2, [%3];"
                     :: "r"(da), "l"(sa), "r"((unsigned)STAGE_A), "r"(bar) : "memory");
        asm volatile("cp.async.bulk.shared::cluster.global.mbarrier::complete_tx::bytes "
                     "[%0], [%1], %2, [%3];"
                     :: "r"(da + STAGE_A), "l"(sb), "r"((unsigned)STAGE_B), "r"(bar) : "memory");
    };

    if (tid == 0) { issue(0, 0); issue(1, 1); issue(2, 2); }

    float acc[2][8][4] = {};
    const unsigned rowA0 = (unsigned)(wm * 32 + g) * 128;
    const unsigned rowB0 = (unsigned)(wn * 64 + g) * 128;

    int s = 0, p = 0;
    #pragma unroll 1
    for (int it = 0; it < NCHUNK; it++) {
        WAITP(mb + s * 8, p);
        unsigned sA = sbase + s * STAGE_T;
        unsigned sB = sA + STAGE_A;
        #pragma unroll
        for (int ks = 0; ks < 4; ks++) {
            unsigned go = ((((unsigned)(2 * tig + (ks >> 1))) ^ (unsigned)g) << 4)
                        + ((ks & 1) << 3);
            unsigned a[2][4];
            #pragma unroll
            for (int f = 0; f < 2; f++) {
                unsigned ad = sA + rowA0 + f * (16 * 128) + go;
                asm volatile("ld.shared.v2.b32 {%0,%1},[%2];"
                             : "=r"(a[f][0]), "=r"(a[f][2]) : "r"(ad));
                asm volatile("ld.shared.v2.b32 {%0,%1},[%2];"
                             : "=r"(a[f][1]), "=r"(a[f][3]) : "r"(ad + 8 * 128));
            }
            #pragma unroll
            for (int c = 0; c < 8; c++) {
                unsigned bd = sB + rowB0 + c * (8 * 128) + go;
                unsigned b[2];
                asm volatile("ld.shared.v2.b32 {%0,%1},[%2];"
                             : "=r"(b[0]), "=r"(b[1]) : "r"(bd));
                mma_tf32(acc[0][c], a[0], b);
                mma_tf32(acc[1][c], a[1], b);
            }
        }
        __syncthreads();
        if (tid == 0 && it + NSTAGE < NCHUNK) issue(it + NSTAGE, s);
        if (++s == NSTAGE) { s = 0; p ^= 1; }
    }

    // epilogue: c0,c1 -> (row g, cols 2tig..); c2,c3 -> row g+8
    #pragma unroll
    for (int f = 0; f < 2; f++) {
        #pragma unroll
        for (int hh = 0; hh < 2; hh++) {
            int m = mt * 256 + wm * 32 + f * 16 + g + hh * 8;
            if (m < M_TOTAL) {
                #pragma unroll
                for (int c = 0; c < 8; c++) {
                    int n = nt * 128 + wn * 64 + c * 8 + tig * 2;
                    float2 v = make_float2(acc[f][c][hh * 2], acc[f][c][hh * 2 + 1]);
                    *reinterpret_cast<float2*>(out + (size_t)m * 1024 + n) = v;
                }
            }
        }
    }
}

extern "C" void kernel_launch(void* const* d_in, const int* in_sizes, int n_in,
                              void* d_out, int out_size) {
    const float* feat = (const float*)d_in[0];   // [47820, 1024] fp32
    const float* W    = (const float*)d_in[1];   // [1024, 4096] fp32
    float* out = (float*)d_out;                  // [11955, 1024] fp32

    prep_B<<<dim3(32, 128), 256>>>(W);
    prep_A<<<dim3(376, 128), 256>>>(feat);

    cudaFuncSetAttribute(merger_gemm,
                         cudaFuncAttributeMaxDynamicSharedMemorySize, SMEM_DYN);
    merger_gemm<<<dim3(8, 47), 512, SMEM_DYN>>>(out);
}